// round 14
// baseline (speedup 1.0000x reference)
#include <cuda_runtime.h>
#include <cstdint>

#define B_  2
#define C_  512
#define NH  8
#define D_  64
#define S_  2304
#define SCALE 0.125f
#define QT  128
#define NCH (S_ / 64)

// ---------------------------------------------------------------------------
__device__ __forceinline__ float tf32r(float f) {
    unsigned r; asm("cvt.rna.tf32.f32 %0, %1;" : "=r"(r) : "f"(f));
    return __uint_as_float(r);
}
__device__ __forceinline__ void mma_tf32(float c[4],
                                         float a0, float a1, float a2, float a3,
                                         float b0, float b1) {
    asm volatile(
        "mma.sync.aligned.m16n8k8.row.col.f32.tf32.tf32.f32 "
        "{%0,%1,%2,%3}, {%4,%5,%6,%7}, {%8,%9}, {%0,%1,%2,%3};\n"
        : "+f"(c[0]), "+f"(c[1]), "+f"(c[2]), "+f"(c[3])
        : "r"(__float_as_uint(a0)), "r"(__float_as_uint(a1)),
          "r"(__float_as_uint(a2)), "r"(__float_as_uint(a3)),
          "r"(__float_as_uint(b0)), "r"(__float_as_uint(b1)));
}

// Scratch ------------------------------------------------------------------
__device__ float g_q[B_ * NH * S_ * D_];    // [bn][s][d]  (scale folded)
__device__ float g_k[B_ * NH * S_ * D_];    // [bn][s][d]
__device__ float g_v[B_ * NH * D_ * S_];    // [bn][d][s]
__device__ float g_attn[B_ * S_ * NH * D_]; // [b][s][n*64+d]

// ===========================================================================
// QKV projection — double-buffered tiles, ONE sync per k-chunk.
// CTA 64d x 64s, warp 32x32, k-chunk 32.  grid (36, 16, 3), block 128.
// ===========================================================================
__global__ __launch_bounds__(128) void proj_kernel(
    const float* __restrict__ x,
    const float* __restrict__ Wq, const float* __restrict__ bq,
    const float* __restrict__ Wk, const float* __restrict__ bk,
    const float* __restrict__ Wv, const float* __restrict__ bv)
{
    __shared__ float sbuf[9216];     // 2 x (As 2304 | Bs 2304); Ts overlays
    float (*Ts)[68] = (float (*)[68])sbuf;

    const int p  = blockIdx.z;
    const int bn = blockIdx.y;
    const int b  = bn >> 3, n = bn & 7;
    const int s0 = blockIdx.x * 64;

    const float* W    = (p == 0) ? Wq : (p == 1) ? Wk : Wv;
    const float* bias = (p == 0) ? bq : (p == 1) ? bk : bv;

    const int tid  = threadIdx.x;
    const int wid  = tid >> 5, lane = tid & 31;
    const int gid  = lane >> 2, tig = lane & 3;
    const int wm   = wid >> 1, wn = wid & 1;

    const float* xb = x + (size_t)b * C_ * S_ + s0;
    const float* Wn = W + n * D_ * C_;

    auto fill = [&](int c, int buf) {
        float (*As)[36] = (float (*)[36])(sbuf + buf * 4608);
        float (*Bs)[72] = (float (*)[72])(sbuf + buf * 4608 + 2304);
        int k0 = c * 32;
        #pragma unroll
        for (int r = 0; r < 4; r++) {
            int i4 = tid + r * 128;
            int dd = i4 >> 3, c4 = (i4 & 7) * 4;
            float4 v = *(const float4*)&Wn[dd * C_ + k0 + c4];
            As[dd][c4]     = tf32r(v.x); As[dd][c4 + 1] = tf32r(v.y);
            As[dd][c4 + 2] = tf32r(v.z); As[dd][c4 + 3] = tf32r(v.w);
        }
        #pragma unroll
        for (int r = 0; r < 4; r++) {
            int i4 = tid + r * 128;
            int cc = i4 >> 4, s4 = (i4 & 15) * 4;
            float4 v = *(const float4*)&xb[(size_t)(k0 + cc) * S_ + s4];
            Bs[cc][s4]     = tf32r(v.x); Bs[cc][s4 + 1] = tf32r(v.y);
            Bs[cc][s4 + 2] = tf32r(v.z); Bs[cc][s4 + 3] = tf32r(v.w);
        }
    };

    float Cacc[2][4][4] = {};

    fill(0, 0);
    __syncthreads();

    for (int c = 0; c < 16; c++) {
        const int cur = c & 1;
        if (c + 1 < 16) fill(c + 1, cur ^ 1);

        float (*As)[36] = (float (*)[36])(sbuf + cur * 4608);
        float (*Bs)[72] = (float (*)[72])(sbuf + cur * 4608 + 2304);

        #pragma unroll
        for (int kk = 0; kk < 32; kk += 8) {
            float a[2][4];
            #pragma unroll
            for (int i = 0; i < 2; i++) {
                int row = wm * 32 + i * 16;
                a[i][0] = As[row + gid][kk + tig];
                a[i][1] = As[row + gid + 8][kk + tig];
                a[i][2] = As[row + gid][kk + tig + 4];
                a[i][3] = As[row + gid + 8][kk + tig + 4];
            }
            #pragma unroll
            for (int j = 0; j < 4; j++) {
                int col = wn * 32 + j * 8 + gid;
                float b0 = Bs[kk + tig][col];
                float b1 = Bs[kk + tig + 4][col];
                #pragma unroll
                for (int i = 0; i < 2; i++)
                    mma_tf32(Cacc[i][j], a[i][0], a[i][1], a[i][2], a[i][3], b0, b1);
            }
        }
        __syncthreads();
    }

    const float qs = (p == 0) ? SCALE : 1.0f;
    if (p == 2) {        // V: [d][s], direct float2
        float* g = g_v + (size_t)bn * D_ * S_;
        #pragma unroll
        for (int i = 0; i < 2; i++) {
            int r0 = wm * 32 + i * 16 + gid;
            float bi0 = bias[n * D_ + r0], bi1 = bias[n * D_ + r0 + 8];
            #pragma unroll
            for (int j = 0; j < 4; j++) {
                int col = s0 + wn * 32 + j * 8 + 2 * tig;
                *(float2*)&g[(size_t)r0 * S_ + col] =
                    make_float2(Cacc[i][j][0] + bi0, Cacc[i][j][1] + bi0);
                *(float2*)&g[(size_t)(r0 + 8) * S_ + col] =
                    make_float2(Cacc[i][j][2] + bi1, Cacc[i][j][3] + bi1);
            }
        }
    } else {             // Q / K: stage [s][d] in smem, coalesced float4 out
        #pragma unroll
        for (int i = 0; i < 2; i++) {
            int r0 = wm * 32 + i * 16 + gid;
            float bi0 = bias[n * D_ + r0], bi1 = bias[n * D_ + r0 + 8];
            #pragma unroll
            for (int j = 0; j < 4; j++) {
                int col = wn * 32 + j * 8 + 2 * tig;
                Ts[col][r0]         = (Cacc[i][j][0] + bi0) * qs;
                Ts[col + 1][r0]     = (Cacc[i][j][1] + bi0) * qs;
                Ts[col][r0 + 8]     = (Cacc[i][j][2] + bi1) * qs;
                Ts[col + 1][r0 + 8] = (Cacc[i][j][3] + bi1) * qs;
            }
        }
        __syncthreads();
        float* g = ((p == 0) ? g_q : g_k) + (size_t)bn * S_ * D_;
        #pragma unroll
        for (int r = 0; r < 8; r++) {
            int i4 = tid + r * 128;
            int ss = i4 >> 4, d4 = (i4 & 15) * 4;
            *(float4*)&g[(size_t)(s0 + ss) * D_ + d4] = *(const float4*)&Ts[ss][d4];
        }
    }
}

// ===========================================================================
// Flash attention: Q fragments IN REGISTERS (smem region reused as 2nd K/V
// buffer), P in registers, j-outer loop (Sc transient), unshifted softmax,
// double-buffered K/V, 1 sync per chunk.
// Smem: region0 = K0(64x72)|V0(64x72); region1 = Qs(128x72) then K1|V1.
// Total 73728 B -> 2 CTAs/SM.  grid (18, 16), block 128.
// ===========================================================================
extern __shared__ float s_at[];

__global__ __launch_bounds__(128) void attn_kernel()
{
    float (*K0)[72] = (float (*)[72])(s_at);
    float (*V0)[72] = (float (*)[72])(s_at + 4608);
    float (*K1)[72] = (float (*)[72])(s_at + 9216);
    float (*V1)[72] = (float (*)[72])(s_at + 13824);
    float (*Qs)[72] = (float (*)[72])(s_at + 9216);   // overlaps buf1

    const int bn = blockIdx.y;
    const int b = bn >> 3, n = bn & 7;
    const int q0 = blockIdx.x * QT;
    const int tid = threadIdx.x;
    const int wid = tid >> 5, lane = tid & 31;
    const int gid = lane >> 2, tig = lane & 3;
    const int qr  = wid * 32;

    const float* Q = g_q + (size_t)bn * S_ * D_;  // [s][d] pre-scaled
    const float* K = g_k + (size_t)bn * S_ * D_;  // [s][d]
    const float* V = g_v + (size_t)bn * D_ * S_;  // [d][s]

    const int ldrow = tid >> 4, ldseg = (tid & 15) * 4;
    auto load_kv = [&](int c, int buf) {
        float (*Kd)[72] = buf ? K1 : K0;
        float (*Vd)[72] = buf ? V1 : V0;
        int k0 = c * 64;
        #pragma unroll
        for (int r = 0; r < 8; r++) {
            int row = ldrow + r * 8;
            *(float4*)&Kd[row][ldseg] = *(const float4*)&K[(size_t)(k0 + row) * D_ + ldseg];
            *(float4*)&Vd[row][ldseg] = *(const float4*)&V[(size_t)row * S_ + k0 + ldseg];
        }
    };

    // stage Q coalesced into Qs, load chunk0 into buf0
    #pragma unroll
    for (int r = 0; r < 16; r++) {
        int i4 = tid + r * 128;
        int row = i4 >> 4, seg = (i4 & 15) * 4;
        *(float4*)&Qs[row][seg] = *(const float4*)&Q[(size_t)(q0 + row) * D_ + seg];
    }
    load_kv(0, 0);
    __syncthreads();

    // Q fragments -> registers (invariant across all 36 chunks)
    float2 qlo[2][8], qhi[2][8];
    #pragma unroll
    for (int kk8 = 0; kk8 < 8; kk8++)
        #pragma unroll
        for (int i = 0; i < 2; i++) {
            int row = qr + i * 16 + gid;
            qlo[i][kk8] = *(const float2*)&Qs[row][kk8 * 8 + 2 * tig];
            qhi[i][kk8] = *(const float2*)&Qs[row + 8][kk8 * 8 + 2 * tig];
        }
    __syncthreads();              // everyone read Q; region1 now free

    float sum[2][2] = {};
    float O[2][8][4] = {};

    for (int c = 0; c < NCH; c++) {
        const int cur = c & 1;
        if (c + 1 < NCH) load_kv(c + 1, cur ^ 1);

        float (*Ksc)[72] = cur ? K1 : K0;
        float (*Vsc)[72] = cur ? V1 : V0;

        #pragma unroll
        for (int j = 0; j < 8; j++) {
            // S column-octet j  (16 mma over kk)
            float Sc[2][4] = {};
            #pragma unroll
            for (int kk8 = 0; kk8 < 8; kk8++) {
                float2 bb = *(const float2*)&Ksc[j * 8 + gid][kk8 * 8 + 2 * tig];
                #pragma unroll
                for (int i = 0; i < 2; i++)
                    mma_tf32(Sc[i], qlo[i][kk8].x, qhi[i][kk8].x,
                             qlo[i][kk8].y, qhi[i][kk8].y, bb.x, bb.y);
            }
            // exp in regs; QK C-frag == PV A-frag (k-permuted)
            float e[2][4];
            #pragma unroll
            for (int i = 0; i < 2; i++) {
                e[i][0] = __expf(Sc[i][0]);
                e[i][1] = __expf(Sc[i][1]);
                e[i][2] = __expf(Sc[i][2]);
                e[i][3] = __expf(Sc[i][3]);
                sum[i][0] += e[i][0] + e[i][1];
                sum[i][1] += e[i][2] + e[i][3];
            }
            #pragma unroll
            for (int nn = 0; nn < 8; nn++) {
                float2 bb = *(const float2*)&Vsc[nn * 8 + gid][j * 8 + 2 * tig];
                #pragma unroll
                for (int i = 0; i < 2; i++)
                    mma_tf32(O[i][nn], e[i][0], e[i][2], e[i][1], e[i][3], bb.x, bb.y);
            }
        }
        __syncthreads();          // compute on cur done; prefetch visible
    }

    float inv[2][2];
    #pragma unroll
    for (int i = 0; i < 2; i++)
        #pragma unroll
        for (int h = 0; h < 2; h++) {
            float s = sum[i][h];
            s += __shfl_xor_sync(0xffffffffu, s, 1);
            s += __shfl_xor_sync(0xffffffffu, s, 2);
            inv[i][h] = 1.f / s;
        }

    float* A = g_attn + ((size_t)b * S_ + q0) * (NH * D_) + n * D_;
    #pragma unroll
    for (int i = 0; i < 2; i++) {
        int row0 = qr + i * 16 + gid;
        #pragma unroll
        for (int j = 0; j < 8; j++) {
            int col = j * 8 + 2 * tig;
            *(float2*)&A[(size_t)row0 * (NH * D_) + col] =
                make_float2(O[i][j][0] * inv[i][0], O[i][j][1] * inv[i][0]);
            *(float2*)&A[(size_t)(row0 + 8) * (NH * D_) + col] =
                make_float2(O[i][j][2] * inv[i][1], O[i][j][3] * inv[i][1]);
        }
    }
}

// ===========================================================================
// Output projection: out^T[s][c] = attn[s][:] . Wo[c][:]^T, double-buffered,
// one sync per chunk.  grid (36, 8, 2), block 128.
// ===========================================================================
__global__ __launch_bounds__(128) void oproj_kernel(
    const float* __restrict__ Wo, const float* __restrict__ bo,
    float* __restrict__ out)
{
    __shared__ float sbuf[10240];   // 2 x (As 2560 | Bs 2560); Ts overlays
    float (*Ts)[68] = (float (*)[68])sbuf;

    const int b  = blockIdx.z;
    const int c0 = blockIdx.y * 64;
    const int s0 = blockIdx.x * 64;

    const int tid = threadIdx.x;
    const int wid = tid >> 5, lane = tid & 31;
    const int gid = lane >> 2, tig = lane & 3;
    const int wm  = wid >> 1, wn = wid & 1;

    const float* A = g_attn + ((size_t)b * S_ + s0) * C_;

    auto fill = [&](int c, int buf) {
        float (*As)[40] = (float (*)[40])(sbuf + buf * 5120);
        float (*Bs)[40] = (float (*)[40])(sbuf + buf * 5120 + 2560);
        int j0 = c * 32;
        #pragma unroll
        for (int r = 0; r < 4; r++) {
            int i4 = tid + r * 128;
            int rr = i4 >> 3, j4 = (i4 & 7) * 4;
            float4 va = *(const float4*)&A[(size_t)rr * C_ + j0 + j4];
            As[rr][j4]     = tf32r(va.x); As[rr][j4 + 1] = tf32r(va.y);
            As[rr][j4 + 2] = tf32r(va.z); As[rr][j4 + 3] = tf32r(va.w);
            float4 vb = *(const float4*)&Wo[(size_t)(c0 + rr) * C_ + j0 + j4];
            Bs[rr][j4]     = tf32r(vb.x); Bs[rr][j4 + 1] = tf32r(vb.y);
            Bs[rr][j4 + 2] = tf32r(vb.z); Bs[rr][j4 + 3] = tf32r(vb.w);
        }
    };

    float Cacc[2][4][4] = {};

    fill(0, 0);
    __syncthreads();

    for (int c = 0; c < 16; c++) {
        const int cur = c & 1;
        if (c + 1 < 16) fill(c + 1, cur ^ 1);

        float (*As)[40] = (float (*)[40])(sbuf + cur * 5120);
        float (*Bs)[40] = (float (*)[40])(sbuf + cur * 5120 + 2560);

        #pragma unroll
        for (int kk = 0; kk < 32; kk += 8) {
            float2 alo[2], ahi[2];
            #pragma unroll
            for (int i = 0; i < 2; i++) {
                int row = wm * 32 + i * 16 + gid;
                alo[i] = *(const float2*)&As[row][kk + 2 * tig];
                ahi[i] = *(const float2*)&As[row + 8][kk + 2 * tig];
            }
            #pragma unroll
            for (int j = 0; j < 4; j++) {
                float2 bb = *(const float2*)&Bs[wn * 32 + j * 8 + gid][kk + 2 * tig];
                #pragma unroll
                for (int i = 0; i < 2; i++)
                    mma_tf32(Cacc[i][j], alo[i].x, ahi[i].x, alo[i].y, ahi[i].y, bb.x, bb.y);
            }
        }
        __syncthreads();
    }

    #pragma unroll
    for (int i = 0; i < 2; i++) {
        int r0 = wm * 32 + i * 16 + gid;              // local s
        #pragma unroll
        for (int j = 0; j < 4; j++) {
            int cl = wn * 32 + j * 8 + 2 * tig;       // local c
            float b0 = bo[c0 + cl], b1 = bo[c0 + cl + 1];
            Ts[cl][r0]         = Cacc[i][j][0] + b0;
            Ts[cl + 1][r0]     = Cacc[i][j][1] + b1;
            Ts[cl][r0 + 8]     = Cacc[i][j][2] + b0;
            Ts[cl + 1][r0 + 8] = Cacc[i][j][3] + b1;
        }
    }
    __syncthreads();
    float* ob = out + ((size_t)b * C_ + c0) * S_ + s0;
    #pragma unroll
    for (int r = 0; r < 8; r++) {
        int i4 = tid + r * 128;
        int cc = i4 >> 4, s4 = (i4 & 15) * 4;
        *(float4*)&ob[(size_t)cc * S_ + s4] = *(const float4*)&Ts[cc][s4];
    }
}

// ---------------------------------------------------------------------------
extern "C" void kernel_launch(void* const* d_in, const int* in_sizes, int n_in,
                              void* d_out, int out_size)
{
    const float* x  = (const float*)d_in[0];
    const float* Wq = (const float*)d_in[1];
    const float* bq = (const float*)d_in[2];
    const float* Wk = (const float*)d_in[3];
    const float* bk = (const float*)d_in[4];
    const float* Wv = (const float*)d_in[5];
    const float* bv = (const float*)d_in[6];
    const float* Wo = (const float*)d_in[7];
    const float* bo = (const float*)d_in[8];
    float* out = (float*)d_out;

    const int attn_smem = 18432 * sizeof(float);   // 73728
    cudaFuncSetAttribute(attn_kernel,
                         cudaFuncAttributeMaxDynamicSharedMemorySize, attn_smem);

    proj_kernel <<<dim3(S_ / 64, B_ * NH, 3), 128>>>(x, Wq, bq, Wk, bk, Wv, bv);
    attn_kernel <<<dim3(S_ / QT, B_ * NH), 128, attn_smem>>>();
    oproj_kernel<<<dim3(S_ / 64, C_ / 64, B_), 128>>>(Wo, bo, out);
}

// round 15
// speedup vs baseline: 1.1225x; 1.1225x over previous
#include <cuda_runtime.h>
#include <cstdint>

#define B_  2
#define C_  512
#define NH  8
#define D_  64
#define S_  2304
#define SCALE 0.125f
#define QT  128
#define NCH (S_ / 64)

// ---------------------------------------------------------------------------
__device__ __forceinline__ float tf32r(float f) {
    unsigned r; asm("cvt.rna.tf32.f32 %0, %1;" : "=r"(r) : "f"(f));
    return __uint_as_float(r);
}
__device__ __forceinline__ void mma_tf32(float c[4],
                                         float a0, float a1, float a2, float a3,
                                         float b0, float b1) {
    asm volatile(
        "mma.sync.aligned.m16n8k8.row.col.f32.tf32.tf32.f32 "
        "{%0,%1,%2,%3}, {%4,%5,%6,%7}, {%8,%9}, {%0,%1,%2,%3};\n"
        : "+f"(c[0]), "+f"(c[1]), "+f"(c[2]), "+f"(c[3])
        : "r"(__float_as_uint(a0)), "r"(__float_as_uint(a1)),
          "r"(__float_as_uint(a2)), "r"(__float_as_uint(a3)),
          "r"(__float_as_uint(b0)), "r"(__float_as_uint(b1)));
}
__device__ __forceinline__ void cpasync16(uint32_t s, const void* g) {
    asm volatile("cp.async.cg.shared.global [%0], [%1], 16;" :: "r"(s), "l"(g));
}
#define CP_COMMIT() asm volatile("cp.async.commit_group;" ::: "memory")
#define CP_WAIT0()  asm volatile("cp.async.wait_group 0;" ::: "memory")

// Scratch ------------------------------------------------------------------
__device__ float g_q[B_ * NH * S_ * D_];    // [bn][s][d]  (scale folded)
__device__ float g_k[B_ * NH * S_ * D_];    // [bn][s][d]
__device__ float g_v[B_ * NH * D_ * S_];    // [bn][d][s]
__device__ float g_attn[B_ * S_ * NH * D_]; // [b][s][n*64+d]

// ===========================================================================
// QKV projection — R13 single-buffered form (known 68.5 us).
// CTA 64d x 64s, warp 32x32, k-chunk 32.  grid (36, 16, 3), block 128.
// ===========================================================================
__global__ __launch_bounds__(128) void proj_kernel(
    const float* __restrict__ x,
    const float* __restrict__ Wq, const float* __restrict__ bq,
    const float* __restrict__ Wk, const float* __restrict__ bk,
    const float* __restrict__ Wv, const float* __restrict__ bv)
{
    __shared__ float sbuf[4608];                 // As(2304) | Bs(2304); Ts(4352)
    float (*As)[36] = (float (*)[36])sbuf;
    float (*Bs)[72] = (float (*)[72])(sbuf + 2304);
    float (*Ts)[68] = (float (*)[68])sbuf;       // epilogue staging [s][d]

    const int p  = blockIdx.z;
    const int bn = blockIdx.y;
    const int b  = bn >> 3, n = bn & 7;
    const int s0 = blockIdx.x * 64;

    const float* W    = (p == 0) ? Wq : (p == 1) ? Wk : Wv;
    const float* bias = (p == 0) ? bq : (p == 1) ? bk : bv;

    const int tid  = threadIdx.x;
    const int wid  = tid >> 5, lane = tid & 31;
    const int gid  = lane >> 2, tig = lane & 3;
    const int wm   = wid >> 1, wn = wid & 1;

    const float* xb = x + (size_t)b * C_ * S_ + s0;
    const float* Wn = W + n * D_ * C_;

    float Cacc[2][4][4] = {};

    for (int k0 = 0; k0 < C_; k0 += 32) {
        #pragma unroll
        for (int r = 0; r < 4; r++) {
            int i4 = tid + r * 128;
            int dd = i4 >> 3, c4 = (i4 & 7) * 4;
            float4 v = *(const float4*)&Wn[dd * C_ + k0 + c4];
            As[dd][c4]     = tf32r(v.x); As[dd][c4 + 1] = tf32r(v.y);
            As[dd][c4 + 2] = tf32r(v.z); As[dd][c4 + 3] = tf32r(v.w);
        }
        #pragma unroll
        for (int r = 0; r < 4; r++) {
            int i4 = tid + r * 128;
            int cc = i4 >> 4, s4 = (i4 & 15) * 4;
            float4 v = *(const float4*)&xb[(size_t)(k0 + cc) * S_ + s4];
            Bs[cc][s4]     = tf32r(v.x); Bs[cc][s4 + 1] = tf32r(v.y);
            Bs[cc][s4 + 2] = tf32r(v.z); Bs[cc][s4 + 3] = tf32r(v.w);
        }
        __syncthreads();

        #pragma unroll
        for (int kk = 0; kk < 32; kk += 8) {
            float a[2][4];
            #pragma unroll
            for (int i = 0; i < 2; i++) {
                int row = wm * 32 + i * 16;
                a[i][0] = As[row + gid][kk + tig];
                a[i][1] = As[row + gid + 8][kk + tig];
                a[i][2] = As[row + gid][kk + tig + 4];
                a[i][3] = As[row + gid + 8][kk + tig + 4];
            }
            #pragma unroll
            for (int j = 0; j < 4; j++) {
                int col = wn * 32 + j * 8 + gid;
                float b0 = Bs[kk + tig][col];
                float b1 = Bs[kk + tig + 4][col];
                #pragma unroll
                for (int i = 0; i < 2; i++)
                    mma_tf32(Cacc[i][j], a[i][0], a[i][1], a[i][2], a[i][3], b0, b1);
            }
        }
        __syncthreads();
    }

    const float qs = (p == 0) ? SCALE : 1.0f;
    if (p == 2) {        // V: [d][s], direct float2
        float* g = g_v + (size_t)bn * D_ * S_;
        #pragma unroll
        for (int i = 0; i < 2; i++) {
            int r0 = wm * 32 + i * 16 + gid;
            float bi0 = bias[n * D_ + r0], bi1 = bias[n * D_ + r0 + 8];
            #pragma unroll
            for (int j = 0; j < 4; j++) {
                int col = s0 + wn * 32 + j * 8 + 2 * tig;
                *(float2*)&g[(size_t)r0 * S_ + col] =
                    make_float2(Cacc[i][j][0] + bi0, Cacc[i][j][1] + bi0);
                *(float2*)&g[(size_t)(r0 + 8) * S_ + col] =
                    make_float2(Cacc[i][j][2] + bi1, Cacc[i][j][3] + bi1);
            }
        }
    } else {             // Q / K: stage [s][d] in smem, coalesced float4 out
        #pragma unroll
        for (int i = 0; i < 2; i++) {
            int r0 = wm * 32 + i * 16 + gid;
            float bi0 = bias[n * D_ + r0], bi1 = bias[n * D_ + r0 + 8];
            #pragma unroll
            for (int j = 0; j < 4; j++) {
                int col = wn * 32 + j * 8 + 2 * tig;     // local s
                Ts[col][r0]         = (Cacc[i][j][0] + bi0) * qs;
                Ts[col + 1][r0]     = (Cacc[i][j][1] + bi0) * qs;
                Ts[col][r0 + 8]     = (Cacc[i][j][2] + bi1) * qs;
                Ts[col + 1][r0 + 8] = (Cacc[i][j][3] + bi1) * qs;
            }
        }
        __syncthreads();
        float* g = ((p == 0) ? g_q : g_k) + (size_t)bn * S_ * D_;
        #pragma unroll
        for (int r = 0; r < 8; r++) {
            int i4 = tid + r * 128;
            int ss = i4 >> 4, d4 = (i4 & 15) * 4;
            *(float4*)&g[(size_t)(s0 + ss) * D_ + d4] = *(const float4*)&Ts[ss][d4];
        }
    }
}

// ===========================================================================
// Flash attention: Q frags in regs, P in regs, j-outer, unshifted softmax,
// double-buffered K/V prefetched via cp.async (no register staging).
// Smem: K0|V0 (9216 f) then K1|V1 (9216 f, Qs overlays) = 73728 B -> 2 CTAs/SM.
// grid (18, 16), block 128.
// ===========================================================================
extern __shared__ float s_at[];

__global__ __launch_bounds__(128) void attn_kernel()
{
    float (*K0)[72] = (float (*)[72])(s_at);
    float (*V0)[72] = (float (*)[72])(s_at + 4608);
    float (*K1)[72] = (float (*)[72])(s_at + 9216);
    float (*V1)[72] = (float (*)[72])(s_at + 13824);
    float (*Qs)[72] = (float (*)[72])(s_at + 9216);   // overlaps buf1

    const int bn = blockIdx.y;
    const int b = bn >> 3, n = bn & 7;
    const int q0 = blockIdx.x * QT;
    const int tid = threadIdx.x;
    const int wid = tid >> 5, lane = tid & 31;
    const int gid = lane >> 2, tig = lane & 3;
    const int qr  = wid * 32;

    const float* Q = g_q + (size_t)bn * S_ * D_;  // [s][d] pre-scaled
    const float* K = g_k + (size_t)bn * S_ * D_;  // [s][d]
    const float* V = g_v + (size_t)bn * D_ * S_;  // [d][s]

    const int ldrow = tid >> 4, ldseg = (tid & 15) * 4;
    const uint32_t sK0 = (uint32_t)__cvta_generic_to_shared(&K0[0][0]);
    const uint32_t sV0 = (uint32_t)__cvta_generic_to_shared(&V0[0][0]);
    const uint32_t sK1 = (uint32_t)__cvta_generic_to_shared(&K1[0][0]);
    const uint32_t sV1 = (uint32_t)__cvta_generic_to_shared(&V1[0][0]);

    auto load_kv_async = [&](int c, int buf) {
        uint32_t sk = buf ? sK1 : sK0;
        uint32_t sv = buf ? sV1 : sV0;
        int k0 = c * 64;
        #pragma unroll
        for (int r = 0; r < 8; r++) {
            int row = ldrow + r * 8;
            uint32_t off = (uint32_t)(row * 72 + ldseg) * 4;
            cpasync16(sk + off, &K[(size_t)(k0 + row) * D_ + ldseg]);
            cpasync16(sv + off, &V[(size_t)row * S_ + k0 + ldseg]);
        }
        CP_COMMIT();
    };

    // chunk0 -> buf0 (async), Q -> Qs (normal stores; Qs overlays buf1)
    load_kv_async(0, 0);
    #pragma unroll
    for (int r = 0; r < 16; r++) {
        int i4 = tid + r * 128;
        int row = i4 >> 4, seg = (i4 & 15) * 4;
        *(float4*)&Qs[row][seg] = *(const float4*)&Q[(size_t)(q0 + row) * D_ + seg];
    }
    CP_WAIT0();
    __syncthreads();

    // Q fragments -> registers (invariant across all 36 chunks)
    float2 qlo[2][8], qhi[2][8];
    #pragma unroll
    for (int kk8 = 0; kk8 < 8; kk8++)
        #pragma unroll
        for (int i = 0; i < 2; i++) {
            int row = qr + i * 16 + gid;
            qlo[i][kk8] = *(const float2*)&Qs[row][kk8 * 8 + 2 * tig];
            qhi[i][kk8] = *(const float2*)&Qs[row + 8][kk8 * 8 + 2 * tig];
        }
    __syncthreads();              // everyone read Q; region1 now free

    float sum[2][2] = {};
    float O[2][8][4] = {};

    for (int c = 0; c < NCH; c++) {
        const int cur = c & 1;
        if (c + 1 < NCH) load_kv_async(c + 1, cur ^ 1);

        float (*Ksc)[72] = cur ? K1 : K0;
        float (*Vsc)[72] = cur ? V1 : V0;

        #pragma unroll
        for (int j = 0; j < 8; j++) {
            float Sc[2][4] = {};
            #pragma unroll
            for (int kk8 = 0; kk8 < 8; kk8++) {
                float2 bb = *(const float2*)&Ksc[j * 8 + gid][kk8 * 8 + 2 * tig];
                #pragma unroll
                for (int i = 0; i < 2; i++)
                    mma_tf32(Sc[i], qlo[i][kk8].x, qhi[i][kk8].x,
                             qlo[i][kk8].y, qhi[i][kk8].y, bb.x, bb.y);
            }
            float e[2][4];
            #pragma unroll
            for (int i = 0; i < 2; i++) {
                e[i][0] = __expf(Sc[i][0]);
                e[i][1] = __expf(Sc[i][1]);
                e[i][2] = __expf(Sc[i][2]);
                e[i][3] = __expf(Sc[i][3]);
                sum[i][0] += e[i][0] + e[i][1];
                sum[i][1] += e[i][2] + e[i][3];
            }
            #pragma unroll
            for (int nn = 0; nn < 8; nn++) {
                float2 bb = *(const float2*)&Vsc[nn * 8 + gid][j * 8 + 2 * tig];
                #pragma unroll
                for (int i = 0; i < 2; i++)
                    mma_tf32(O[i][nn], e[i][0], e[i][2], e[i][1], e[i][3], bb.x, bb.y);
            }
        }
        CP_WAIT0();
        __syncthreads();          // compute on cur done; prefetch landed
    }

    float inv[2][2];
    #pragma unroll
    for (int i = 0; i < 2; i++)
        #pragma unroll
        for (int h = 0; h < 2; h++) {
            float s = sum[i][h];
            s += __shfl_xor_sync(0xffffffffu, s, 1);
            s += __shfl_xor_sync(0xffffffffu, s, 2);
            inv[i][h] = 1.f / s;
        }

    float* A = g_attn + ((size_t)b * S_ + q0) * (NH * D_) + n * D_;
    #pragma unroll
    for (int i = 0; i < 2; i++) {
        int row0 = qr + i * 16 + gid;
        #pragma unroll
        for (int j = 0; j < 8; j++) {
            int col = j * 8 + 2 * tig;
            *(float2*)&A[(size_t)row0 * (NH * D_) + col] =
                make_float2(O[i][j][0] * inv[i][0], O[i][j][1] * inv[i][0]);
            *(float2*)&A[(size_t)(row0 + 8) * (NH * D_) + col] =
                make_float2(O[i][j][2] * inv[i][1], O[i][j][3] * inv[i][1]);
        }
    }
}

// ===========================================================================
// Output projection (R14 double-buffered version).
// ===========================================================================
__global__ __launch_bounds__(128) void oproj_kernel(
    const float* __restrict__ Wo, const float* __restrict__ bo,
    float* __restrict__ out)
{
    __shared__ float sbuf[10240];   // 2 x (As 2560 | Bs 2560); Ts overlays
    float (*Ts)[68] = (float (*)[68])sbuf;

    const int b  = blockIdx.z;
    const int c0 = blockIdx.y * 64;
    const int s0 = blockIdx.x * 64;

    const int tid = threadIdx.x;
    const int wid = tid >> 5, lane = tid & 31;
    const int gid = lane >> 2, tig = lane & 3;
    const int wm  = wid >> 1, wn = wid & 1;

    const float* A = g_attn + ((size_t)b * S_ + s0) * C_;

    auto fill = [&](int c, int buf) {
        float (*As)[40] = (float (*)[40])(sbuf + buf * 5120);
        float (*Bs)[40] = (float (*)[40])(sbuf + buf * 5120 + 2560);
        int j0 = c * 32;
        #pragma unroll
        for (int r = 0; r < 4; r++) {
            int i4 = tid + r * 128;
            int rr = i4 >> 3, j4 = (i4 & 7) * 4;
            float4 va = *(const float4*)&A[(size_t)rr * C_ + j0 + j4];
            As[rr][j4]     = tf32r(va.x); As[rr][j4 + 1] = tf32r(va.y);
            As[rr][j4 + 2] = tf32r(va.z); As[rr][j4 + 3] = tf32r(va.w);
            float4 vb = *(const float4*)&Wo[(size_t)(c0 + rr) * C_ + j0 + j4];
            Bs[rr][j4]     = tf32r(vb.x); Bs[rr][j4 + 1] = tf32r(vb.y);
            Bs[rr][j4 + 2] = tf32r(vb.z); Bs[rr][j4 + 3] = tf32r(vb.w);
        }
    };

    float Cacc[2][4][4] = {};

    fill(0, 0);
    __syncthreads();

    for (int c = 0; c < 16; c++) {
        const int cur = c & 1;
        if (c + 1 < 16) fill(c + 1, cur ^ 1);

        float (*As)[40] = (float (*)[40])(sbuf + cur * 5120);
        float (*Bs)[40] = (float (*)[40])(sbuf + cur * 5120 + 2560);

        #pragma unroll
        for (int kk = 0; kk < 32; kk += 8) {
            float2 alo[2], ahi[2];
            #pragma unroll
            for (int i = 0; i < 2; i++) {
                int row = wm * 32 + i * 16 + gid;
                alo[i] = *(const float2*)&As[row][kk + 2 * tig];
                ahi[i] = *(const float2*)&As[row + 8][kk + 2 * tig];
            }
            #pragma unroll
            for (int j = 0; j < 4; j++) {
                float2 bb = *(const float2*)&Bs[wn * 32 + j * 8 + gid][kk + 2 * tig];
                #pragma unroll
                for (int i = 0; i < 2; i++)
                    mma_tf32(Cacc[i][j], alo[i].x, ahi[i].x, alo[i].y, ahi[i].y, bb.x, bb.y);
            }
        }
        __syncthreads();
    }

    #pragma unroll
    for (int i = 0; i < 2; i++) {
        int r0 = wm * 32 + i * 16 + gid;              // local s
        #pragma unroll
        for (int j = 0; j < 4; j++) {
            int cl = wn * 32 + j * 8 + 2 * tig;       // local c
            float b0 = bo[c0 + cl], b1 = bo[c0 + cl + 1];
            Ts[cl][r0]         = Cacc[i][j][0] + b0;
            Ts[cl + 1][r0]     = Cacc[i][j][1] + b1;
            Ts[cl][r0 + 8]     = Cacc[i][j][2] + b0;
            Ts[cl + 1][r0 + 8] = Cacc[i][j][3] + b1;
        }
    }
    __syncthreads();
    float* ob = out + ((size_t)b * C_ + c0) * S_ + s0;
    #pragma unroll
    for (int r = 0; r < 8; r++) {
        int i4 = tid + r * 128;
        int cc = i4 >> 4, s4 = (i4 & 15) * 4;
        *(float4*)&ob[(size_t)cc * S_ + s4] = *(const float4*)&Ts[cc][s4];
    }
}

// ---------------------------------------------------------------------------
extern "C" void kernel_launch(void* const* d_in, const int* in_sizes, int n_in,
                              void* d_out, int out_size)
{
    const float* x  = (const float*)d_in[0];
    const float* Wq = (const float*)d_in[1];
    const float* bq = (const float*)d_in[2];
    const float* Wk = (const float*)d_in[3];
    const float* bk = (const float*)d_in[4];
    const float* Wv = (const float*)d_in[5];
    const float* bv = (const float*)d_in[6];
    const float* Wo = (const float*)d_in[7];
    const float* bo = (const float*)d_in[8];
    float* out = (float*)d_out;

    const int attn_smem = 18432 * sizeof(float);   // 73728
    cudaFuncSetAttribute(attn_kernel,
                         cudaFuncAttributeMaxDynamicSharedMemorySize, attn_smem);

    proj_kernel <<<dim3(S_ / 64, B_ * NH, 3), 128>>>(x, Wq, bq, Wk, bk, Wv, bv);
    attn_kernel <<<dim3(S_ / QT, B_ * NH), 128, attn_smem>>>();
    oproj_kernel<<<dim3(S_ / 64, C_ / 64, B_), 128>>>(Wo, bo, out);
}